// round 4
// baseline (speedup 1.0000x reference)
#include <cuda_runtime.h>
#include <cstdint>
#include <math.h>

// ---------------------------------------------------------------------------
// NeuralODE Tsit5 — persistent-CTA fp32 kernel, round 3.
// 512 threads/CTA (4 warps/SMSP), transposed activations [N][TM].
// k-loop: 1x LDS.128 (A row-pairs, packed u64) + 1x LDS.128 (W float4)
//         -> 8x fma.rn.f32x2 per thread per k. 2 wavefronts / 16 FMA-cyc.
// ---------------------------------------------------------------------------

#define BATCH   4096
#define DIM     64
#define WIDTH   256
#define NTT     101
#define TM      32
#define NCTA    (BATCH / TM)      // 128
#define THREADS 512

#define WTILE      8192                // floats per W tile (32KB)
#define WBUF_SIZE  (2 * WTILE)
#define ACT_SIZE   (WIDTH * TM)        // 8192 floats, transposed [N][TM]
#define ZK_SIZE    (DIM * TM)          // 2048 floats, transposed [DIM][TM]

#define SMEM_FLOATS (2*ACT_SIZE + WBUF_SIZE + ZK_SIZE + ZK_SIZE + 6*ZK_SIZE)
#define SMEM_BYTES  (SMEM_FLOATS * 4)   // 196608 B

// Tsit5 tableau
__constant__ float c_A[6][5] = {
    {0.f, 0.f, 0.f, 0.f, 0.f},
    {0.161f, 0.f, 0.f, 0.f, 0.f},
    {-0.008480655492356989f, 0.335480655492357f, 0.f, 0.f, 0.f},
    {2.8971530571054935f, -6.359448489975075f, 4.3622954328695815f, 0.f, 0.f},
    {5.325864828439257f, -11.748883564062828f, 7.4955393428898365f, -0.09249506636175525f, 0.f},
    {5.86145544294642f, -12.92096931784711f, 8.159367898576159f, -0.071584973281401f, -0.028269050394068383f}
};
__constant__ float c_B[6] = {
    0.09646076681806523f, 0.01f, 0.4798896504144996f,
    1.379008574103742f, -3.290069515436081f, 2.324710524099774f
};

// ---- packed f32x2 helpers ----
__device__ __forceinline__ unsigned long long pk2(float lo, float hi) {
    unsigned long long r;
    asm("mov.b64 %0, {%1, %2};" : "=l"(r) : "f"(lo), "f"(hi));
    return r;
}
__device__ __forceinline__ void upk2(unsigned long long v, float &lo, float &hi) {
    asm("mov.b64 {%0, %1}, %2;" : "=f"(lo), "=f"(hi) : "l"(v));
}
__device__ __forceinline__ void ffma2(unsigned long long &d,
                                      unsigned long long a,
                                      unsigned long long b) {
    asm("fma.rn.f32x2 %0, %1, %2, %0;" : "+l"(d) : "l"(a), "l"(b));
}

// ---- cp.async helpers ----
__device__ __forceinline__ void cpa16(float *smem_dst, const float *gmem_src) {
    unsigned s = (unsigned)__cvta_generic_to_shared(smem_dst);
    asm volatile("cp.async.cg.shared.global [%0], [%1], 16;" :: "r"(s), "l"(gmem_src));
}
__device__ __forceinline__ void cpa_commit() {
    asm volatile("cp.async.commit_group;");
}
template <int N>
__device__ __forceinline__ void cpa_wait() {
    asm volatile("cp.async.wait_group %0;" :: "n"(N));
}

// ---------------------------------------------------------------------------
// Dense layer on transposed activations:
//   O^T[N][TM] = act( W^T . A^T + b ),  A/O in SMEM as [n*TM + m].
// Thread map: rg = tid&7 (8 row-groups x 4 rows), cg = tid>>3 (64 col-groups).
// Per warp: rg spans all 8 groups, cg spans 4 -> every LDS is 1 wavefront.
// ---------------------------------------------------------------------------
template <int K, int N, bool ACT>
__device__ __forceinline__ void layerT(const float *__restrict__ A,
                                       float *__restrict__ O,
                                       const float *__restrict__ Wg,
                                       const float *__restrict__ bg,
                                       float *__restrict__ wbuf) {
    constexpr int KC    = WTILE / N;   // 32 (N=256) or 128 (N=64)
    constexpr int TILES = K / KC;      // L0:2  L1/L2:8  L3:2
    constexpr int CT    = (N >= 256) ? 4 : 1;

    const int tid = threadIdx.x;
    const int rg  = tid & 7;           // 8 row-groups of 4 rows
    const int cg  = tid >> 3;          // 0..63
    const int r0  = rg * 4;
    const int c0  = cg * CT;

    unsigned long long acc[2][CT];
#pragma unroll
    for (int c = 0; c < CT; c++) {
        float b = __ldg(bg + c0 + c);
        unsigned long long bb = pk2(b, b);
        acc[0][c] = bb;
        acc[1][c] = bb;
    }

    // prefetch W tile 0
    for (int i = tid; i < WTILE / 4; i += THREADS)
        cpa16(wbuf + i * 4, Wg + i * 4);
    cpa_commit();

#pragma unroll
    for (int tile = 0; tile < TILES; ++tile) {
        if (tile + 1 < TILES) {
            const float *src = Wg + (tile + 1) * WTILE;
            float *dst = wbuf + ((tile + 1) & 1) * WTILE;
            for (int i = tid; i < WTILE / 4; i += THREADS)
                cpa16(dst + i * 4, src + i * 4);
            cpa_commit();
            cpa_wait<1>();
        } else {
            cpa_wait<0>();
        }
        __syncthreads();

        const float *Wt = wbuf + (tile & 1) * WTILE;
        const float *At = A + tile * KC * TM + r0;

#pragma unroll 8
        for (int k = 0; k < KC; k++) {
            // 4 rows of column k, packed as 2 f32x2 pairs (16B aligned)
            ulonglong2 a = *reinterpret_cast<const ulonglong2 *>(At + k * TM);
            unsigned long long ap0 = a.x, ap1 = a.y;

            if constexpr (CT == 4) {
                float4 w = *reinterpret_cast<const float4 *>(Wt + k * N + c0);
                unsigned long long w0 = pk2(w.x, w.x);
                unsigned long long w1 = pk2(w.y, w.y);
                unsigned long long w2 = pk2(w.z, w.z);
                unsigned long long w3 = pk2(w.w, w.w);
                ffma2(acc[0][0], ap0, w0); ffma2(acc[1][0], ap1, w0);
                ffma2(acc[0][1], ap0, w1); ffma2(acc[1][1], ap1, w1);
                ffma2(acc[0][2], ap0, w2); ffma2(acc[1][2], ap1, w2);
                ffma2(acc[0][3], ap0, w3); ffma2(acc[1][3], ap1, w3);
            } else {
                float w = Wt[k * N + c0];
                unsigned long long w0 = pk2(w, w);
                ffma2(acc[0][0], ap0, w0);
                ffma2(acc[1][0], ap1, w0);
            }
        }
        __syncthreads();
    }

    // epilogue: tanh + store transposed (float2 per row-pair)
#pragma unroll
    for (int c = 0; c < CT; c++) {
#pragma unroll
        for (int p = 0; p < 2; p++) {
            float x0, x1;
            upk2(acc[p][c], x0, x1);
            if (ACT) { x0 = tanhf(x0); x1 = tanhf(x1); }
            float2 v; v.x = x0; v.y = x1;
            *reinterpret_cast<float2 *>(O + (c0 + c) * TM + r0 + 2 * p) = v;
        }
    }
}

// ---------------------------------------------------------------------------
__global__ void __launch_bounds__(THREADS, 1)
node_kernel(const float *__restrict__ ts, const float *__restrict__ y0,
            const float *__restrict__ W0, const float *__restrict__ b0,
            const float *__restrict__ W1, const float *__restrict__ b1,
            const float *__restrict__ W2, const float *__restrict__ b2,
            const float *__restrict__ W3, const float *__restrict__ b3,
            float *__restrict__ out) {
    extern __shared__ float sm[];
    float *act0 = sm;                       // 8192 (transposed [256][32])
    float *act1 = act0 + ACT_SIZE;          // 8192
    float *wbuf = act1 + ACT_SIZE;          // 16384
    float *zbuf = wbuf + WBUF_SIZE;         // 2048  (transposed [64][32])
    float *ybuf = zbuf + ZK_SIZE;           // 2048
    float *kbuf = ybuf + ZK_SIZE;           // 6 * 2048

    const int tid = threadIdx.x;
    const int cta = blockIdx.x;

    // ingest y0 (row-major) -> ybuf (transposed); emit out[0]
    {
        const float *y0c = y0 + (size_t)cta * TM * DIM;
        float *o0 = out + (size_t)cta * TM * DIM;
        for (int i = tid; i < TM * DIM; i += THREADS) {
            float v = __ldg(y0c + i);
            int m = i >> 6;          // DIM = 64
            int d = i & 63;
            ybuf[d * TM + m] = v;
            o0[i] = v;
        }
    }
    __syncthreads();

    for (int t = 1; t < NTT; ++t) {
        const float h = __ldg(ts + t) - __ldg(ts + t - 1);

        for (int s = 0; s < 6; ++s) {
            const float *zin;
            if (s == 0) {
                zin = ybuf;          // z == y for stage 0
            } else {
                // z = y + h * sum_{j<s} A[s][j] * k_j   (transposed, contiguous)
                float4 *zb = reinterpret_cast<float4 *>(zbuf);
                const float4 *yb = reinterpret_cast<const float4 *>(ybuf);
                for (int i = tid; i < ZK_SIZE / 4; i += THREADS) {
                    float4 v = yb[i];
                    for (int j = 0; j < s; j++) {
                        float c = h * c_A[s][j];
                        float4 kv = reinterpret_cast<const float4 *>(kbuf + j * ZK_SIZE)[i];
                        v.x += c * kv.x; v.y += c * kv.y;
                        v.z += c * kv.z; v.w += c * kv.w;
                    }
                    zb[i] = v;
                }
                zin = zbuf;
            }
            __syncthreads();

            layerT<DIM,   WIDTH, true >(zin,  act0, W0, b0, wbuf);
            layerT<WIDTH, WIDTH, true >(act0, act1, W1, b1, wbuf);
            layerT<WIDTH, WIDTH, true >(act1, act0, W2, b2, wbuf);
            layerT<WIDTH, DIM,   false>(act0, kbuf + s * ZK_SIZE, W3, b3, wbuf);
            __syncthreads();
        }

        // y += h * sum_j B[j] * k_j   (transposed, contiguous)
        {
            float4 *yb = reinterpret_cast<float4 *>(ybuf);
            for (int i = tid; i < ZK_SIZE / 4; i += THREADS) {
                float4 v = yb[i];
#pragma unroll
                for (int j = 0; j < 6; j++) {
                    float c = h * c_B[j];
                    float4 kv = reinterpret_cast<const float4 *>(kbuf + j * ZK_SIZE)[i];
                    v.x += c * kv.x; v.y += c * kv.y;
                    v.z += c * kv.z; v.w += c * kv.w;
                }
                yb[i] = v;
            }
        }
        __syncthreads();

        // store out[t] (row-major, coalesced float4) from transposed ybuf
        {
            float *outc = out + (size_t)t * (BATCH * DIM) + (size_t)cta * TM * DIM;
            for (int i4 = tid; i4 < TM * DIM / 4; i4 += THREADS) {
                int m  = i4 >> 4;    // 16 float4 per batch row
                int dq = (i4 & 15) * 4;
                float4 v;
                v.x = ybuf[(dq + 0) * TM + m];
                v.y = ybuf[(dq + 1) * TM + m];
                v.z = ybuf[(dq + 2) * TM + m];
                v.w = ybuf[(dq + 3) * TM + m];
                reinterpret_cast<float4 *>(outc)[i4] = v;
            }
        }
        __syncthreads();
    }
}

// ---------------------------------------------------------------------------
extern "C" void kernel_launch(void *const *d_in, const int *in_sizes, int n_in,
                              void *d_out, int out_size) {
    const float *ts = (const float *)d_in[0];
    const float *y0 = (const float *)d_in[1];
    const float *W0 = (const float *)d_in[2];
    const float *b0 = (const float *)d_in[3];
    const float *W1 = (const float *)d_in[4];
    const float *b1 = (const float *)d_in[5];
    const float *W2 = (const float *)d_in[6];
    const float *b2 = (const float *)d_in[7];
    const float *W3 = (const float *)d_in[8];
    const float *b3 = (const float *)d_in[9];
    float *out = (float *)d_out;

    cudaFuncSetAttribute(node_kernel,
                         cudaFuncAttributeMaxDynamicSharedMemorySize, SMEM_BYTES);
    node_kernel<<<NCTA, THREADS, SMEM_BYTES>>>(ts, y0, W0, b0, W1, b1,
                                               W2, b2, W3, b3, out);
}